// round 7
// baseline (speedup 1.0000x reference)
#include <cuda_runtime.h>
#include <cuda_bf16.h>
#include <mma.h>
#include <cstdint>

using namespace nvcuda;

// Problem constants (fixed by setup_inputs)
#define NN 100000   // nodes
#define EE 1000000  // edges
#define DD 64       // input dim
#define HH 128      // embed_dim
#define KK 128      // 2*DD
#define ELL 64      // ELL row stride (max degree ~41 for Poisson(20))

typedef unsigned int u32;

// ---------------- scratch (no allocations allowed) ----------------
__device__ float2        g_mean2[NN * 32];   // neighbor feature MEANS, [N][64] as float2
__device__ int           g_cnt[NN];          // degree counters (slot allocator + final degree)
__device__ int           g_adj[NN * ELL];    // ELL adjacency
__device__ __nv_bfloat16 g_Whi[HH * KK];     // W split hi, row-major [h][k]
__device__ __nv_bfloat16 g_Wlo[HH * KK];     // W split lo

// ---------------- helpers ----------------
// split floats into bf16 hi + bf16 lo, packed pairwise
__device__ __forceinline__ void cvt2_split(float a, float b, u32& hi, u32& lo) {
    __nv_bfloat162 h2 = __floats2bfloat162_rn(a, b);
    float ra = a - __bfloat162float(h2.x);
    float rb = b - __bfloat162float(h2.y);
    __nv_bfloat162 l2 = __floats2bfloat162_rn(ra, rb);
    hi = *reinterpret_cast<u32*>(&h2);
    lo = *reinterpret_cast<u32*>(&l2);
}

// ---------------- kernel 1: zero counters + split W ----------------
__global__ void prep_kernel(const float* __restrict__ W, int n_nodes) {
    int gid = blockIdx.x * blockDim.x + threadIdx.x;
    if (gid < n_nodes) g_cnt[gid] = 0;
    if (gid < HH * KK) {
        float w = W[gid];
        __nv_bfloat16 hb = __float2bfloat16_rn(w);
        float r = w - __bfloat162float(hb);
        g_Whi[gid] = hb;
        g_Wlo[gid] = __float2bfloat16_rn(r);
    }
}

// ---------------- kernel 2: ELL fill (atomicAdd allocates slots) ----------------
__global__ void k_fill(const int* __restrict__ ei, int n_edges) {
    int e = blockIdx.x * blockDim.x + threadIdx.x;
    if (e >= n_edges) return;
    int s = ei[e];
    int d = ei[n_edges + e];
    int p0 = atomicAdd(&g_cnt[s], 1);
    g_adj[s * ELL + p0] = d;
    int p1 = atomicAdd(&g_cnt[d], 1);
    g_adj[d * ELL + p1] = s;
}

// ---------------- kernel 3: gather-reduce: warp per node, writes MEAN ----------------
__global__ __launch_bounds__(256)
void k_gather(const float2* __restrict__ feat2, int n_nodes) {
    int w = (blockIdx.x * blockDim.x + threadIdx.x) >> 5;
    if (w >= n_nodes) return;
    int lane = threadIdx.x & 31;
    int deg = g_cnt[w];
    const int* row = &g_adj[w * ELL];     // 256B aligned

    float2 acc = make_float2(0.f, 0.f);
    int j = 0;
    for (; j + 4 <= deg; j += 4) {
        int4 i4 = *(const int4*)&row[j];  // one LDG.128 for 4 indices
        float2 a = feat2[(size_t)i4.x * 32 + lane];
        float2 b = feat2[(size_t)i4.y * 32 + lane];
        float2 c = feat2[(size_t)i4.z * 32 + lane];
        float2 d = feat2[(size_t)i4.w * 32 + lane];
        acc.x += a.x + b.x + c.x + d.x;
        acc.y += a.y + b.y + c.y + d.y;
    }
    for (; j < deg; ++j) {
        float2 a = feat2[(size_t)row[j] * 32 + lane];
        acc.x += a.x;
        acc.y += a.y;
    }
    float inv = 1.0f / fmaxf((float)deg, 1.0f);
    acc.x *= inv;
    acc.y *= inv;
    g_mean2[(size_t)w * 32 + lane] = acc;
}

// ---------------- kernel 4: wmma GEMM (3xBF16 split), 512 threads ----------------
// out[m][h] = relu( combined[m] . W[h] + b[h] ), via
//   hi@Whi + hi@Wlo + lo@Whi   (fp32 accumulate)
// 16 warps, each computing a 32x32 sub-tile (2x2 fragments).
#define ASTRIDE 136
#define TILE_ELEMS (128 * ASTRIDE)            // 17408 bf16
#define SMEM_DYN (4 * TILE_ELEMS * 2)         // 139264 bytes

__global__ __launch_bounds__(512)
void gemm_kernel(const float4* __restrict__ feat4,
                 const int* __restrict__ nodes,
                 const float* __restrict__ bias,
                 float* __restrict__ out,
                 int n_rows) {
    extern __shared__ __nv_bfloat16 smem[];
    __nv_bfloat16* Ahi = smem;
    __nv_bfloat16* Alo = smem + TILE_ELEMS;
    __nv_bfloat16* Bhi = smem + 2 * TILE_ELEMS;
    __nv_bfloat16* Blo = smem + 3 * TILE_ELEMS;

    int tid = threadIdx.x;
    int block_m = blockIdx.x * 128;

    // ---- stage pre-split W, col-major: Bs[k + h*ASTRIDE] ----
    // u32 = bf16 pair (k, k+1) of one h; dst 4B-aligned (272B row stride).
    {
        const u32* shi = (const u32*)g_Whi;
        const u32* slo = (const u32*)g_Wlo;
        #pragma unroll
        for (int i = 0; i < (HH * KK / 2) / 512; ++i) {
            int idx = tid + i * 512;          // pair index
            int h = idx >> 6;                 // 64 pairs per h
            int k = (idx & 63) * 2;
            *(u32*)&Bhi[k + h * ASTRIDE] = shi[idx];
            *(u32*)&Blo[k + h * ASTRIDE] = slo[idx];
        }
    }

    // ---- gather + split combined rows ----
    // 4 threads per row: sub>>1 = half (0 self, 1 mean), sub&1 = chunk quad
    {
        int r = tid >> 2;
        int sub = tid & 3;
        int half = sub >> 1;
        int qbase = (sub & 1) * 4;
        int row = block_m + r;
        bool valid = row < n_rows;
        int g = valid ? nodes[row] : 0;
        const float4* src = half ? (const float4*)&g_mean2[(size_t)g * 32]
                                 : &feat4[(size_t)g * 16];

        #pragma unroll
        for (int qi = 0; qi < 4; ++qi) {      // 4 chunks of 8 bf16 each
            int q = qbase + qi;
            uint4 hi = make_uint4(0, 0, 0, 0), lo = make_uint4(0, 0, 0, 0);
            if (valid) {
                float4 u = src[2 * q];
                float4 v = src[2 * q + 1];
                cvt2_split(u.x, u.y, hi.x, lo.x);
                cvt2_split(u.z, u.w, hi.y, lo.y);
                cvt2_split(v.x, v.y, hi.z, lo.z);
                cvt2_split(v.z, v.w, hi.w, lo.w);
            }
            int off = r * ASTRIDE + half * 64 + q * 8;
            *(uint4*)&Ahi[off] = hi;
            *(uint4*)&Alo[off] = lo;
        }
    }
    __syncthreads();

    // ---- wmma: warp tile 32x32 (2 x 2 fragments of 16x16), 4x4 warp grid ----
    int wid = tid >> 5;
    int wm = wid & 3;      // 0..3 -> rows wm*32
    int wn = wid >> 2;     // 0..3 -> cols wn*32

    wmma::fragment<wmma::accumulator, 16, 16, 16, float> acc[2][2];
    #pragma unroll
    for (int i = 0; i < 2; ++i)
        #pragma unroll
        for (int j = 0; j < 2; ++j) wmma::fill_fragment(acc[i][j], 0.0f);

    const __nv_bfloat16* Aptr[3] = {Ahi, Ahi, Alo};
    const __nv_bfloat16* Bptr[3] = {Bhi, Blo, Bhi};

    #pragma unroll
    for (int pass = 0; pass < 3; ++pass) {
        const __nv_bfloat16* As = Aptr[pass];
        const __nv_bfloat16* Bs = Bptr[pass];
        #pragma unroll
        for (int k0 = 0; k0 < KK; k0 += 16) {
            wmma::fragment<wmma::matrix_a, 16, 16, 16, __nv_bfloat16, wmma::row_major> af[2];
            wmma::fragment<wmma::matrix_b, 16, 16, 16, __nv_bfloat16, wmma::col_major> bf[2];
            #pragma unroll
            for (int i = 0; i < 2; ++i)
                wmma::load_matrix_sync(af[i], As + (wm * 32 + i * 16) * ASTRIDE + k0, ASTRIDE);
            #pragma unroll
            for (int j = 0; j < 2; ++j)
                wmma::load_matrix_sync(bf[j], Bs + k0 + (wn * 32 + j * 16) * ASTRIDE, ASTRIDE);
            #pragma unroll
            for (int i = 0; i < 2; ++i)
                #pragma unroll
                for (int j = 0; j < 2; ++j)
                    wmma::mma_sync(acc[i][j], af[i], bf[j], acc[i][j]);
        }
    }

    // ---- stage accumulators to smem (reuse tile region), then epilogue ----
    __syncthreads();   // all warps done reading A/B tiles
    float* stage = (float*)smem;                   // 16 warps x 32x32 f32 = 64KB
    float* wstage = stage + wid * (32 * 32);
    #pragma unroll
    for (int i = 0; i < 2; ++i)
        #pragma unroll
        for (int j = 0; j < 2; ++j)
            wmma::store_matrix_sync(wstage + i * 16 * 32 + j * 16, acc[i][j],
                                    32, wmma::mem_row_major);
    __syncwarp();

    // each lane writes one row of the warp tile (32 rows x 32 cols)
    {
        int lane = tid & 31;
        int row = block_m + wm * 32 + lane;
        if (row < n_rows) {
            const float* srow = wstage + lane * 32;
            float* orow = out + (size_t)row * HH + wn * 32;
            #pragma unroll
            for (int c = 0; c < 32; c += 4) {
                float4 o;
                o.x = fmaxf(srow[c + 0] + bias[wn * 32 + c + 0], 0.f);
                o.y = fmaxf(srow[c + 1] + bias[wn * 32 + c + 1], 0.f);
                o.z = fmaxf(srow[c + 2] + bias[wn * 32 + c + 2], 0.f);
                o.w = fmaxf(srow[c + 3] + bias[wn * 32 + c + 3], 0.f);
                *(float4*)&orow[c] = o;
            }
        }
    }
}

// ---------------- launch ----------------
extern "C" void kernel_launch(void* const* d_in, const int* in_sizes, int n_in,
                              void* d_out, int out_size) {
    const int*    nodes    = (const int*)d_in[0];
    const float*  features = (const float*)d_in[1];
    const int*    ei       = (const int*)d_in[2];
    const float*  W        = (const float*)d_in[3];
    const float*  bias     = (const float*)d_in[4];
    float*        out      = (float*)d_out;

    int n_rows  = in_sizes[0];           // B == N
    int n_nodes = in_sizes[1] / DD;      // N
    int n_edges = in_sizes[2] / 2;       // E

    const float4* feat4 = (const float4*)features;
    const float2* feat2 = (const float2*)features;

    // opt-in to >48KB dynamic smem (idempotent, no allocation)
    static bool attr_done = false;
    if (!attr_done) {
        cudaFuncSetAttribute(gemm_kernel,
                             cudaFuncAttributeMaxDynamicSharedMemorySize, SMEM_DYN);
        attr_done = true;
    }

    // 1. zero counters + split W
    {
        int total = n_nodes > HH * KK ? n_nodes : HH * KK;
        prep_kernel<<<(total + 255) / 256, 256>>>(W, n_nodes);
    }
    // 2. ELL fill
    k_fill<<<(n_edges + 255) / 256, 256>>>(ei, n_edges);
    // 3. gather-reduce (writes means)
    k_gather<<<(n_nodes * 32 + 255) / 256, 256>>>(feat2, n_nodes);
    // 4. wmma GEMM (concat fused into gather stage)
    {
        int blocks = (n_rows + 127) / 128;
        gemm_kernel<<<blocks, 512, SMEM_DYN>>>(feat4, nodes, bias, out, n_rows);
    }
}

// round 8
// speedup vs baseline: 1.1525x; 1.1525x over previous
#include <cuda_runtime.h>
#include <cuda_bf16.h>
#include <mma.h>
#include <cstdint>

using namespace nvcuda;

// Problem constants (fixed by setup_inputs)
#define NN 100000   // nodes
#define EE 1000000  // edges
#define DD 64       // input dim
#define HH 128      // embed_dim
#define KK 128      // 2*DD
#define ELL 64      // ELL row stride (max degree ~41 for Poisson(20))

typedef unsigned int u32;

// ---------------- scratch (no allocations allowed) ----------------
__device__ float2        g_mean2[NN * 32];   // neighbor feature MEANS, [N][64] as float2
__device__ int           g_cnt[NN];          // degree counters (slot allocator + final degree)
__device__ int           g_adj[NN * ELL];    // ELL adjacency
__device__ __nv_bfloat16 g_Whi[HH * KK];     // W split hi, row-major [h][k]
__device__ __nv_bfloat16 g_Wlo[HH * KK];     // W split lo

// ---------------- helpers ----------------
// split floats into bf16 hi + bf16 lo, packed pairwise
__device__ __forceinline__ void cvt2_split(float a, float b, u32& hi, u32& lo) {
    __nv_bfloat162 h2 = __floats2bfloat162_rn(a, b);
    float ra = a - __bfloat162float(h2.x);
    float rb = b - __bfloat162float(h2.y);
    __nv_bfloat162 l2 = __floats2bfloat162_rn(ra, rb);
    hi = *reinterpret_cast<u32*>(&h2);
    lo = *reinterpret_cast<u32*>(&l2);
}

// ---------------- kernel 1: zero counters + split W ----------------
__global__ void prep_kernel(const float* __restrict__ W, int n_nodes) {
    int gid = blockIdx.x * blockDim.x + threadIdx.x;
    if (gid < n_nodes) g_cnt[gid] = 0;
    if (gid < HH * KK) {
        float w = W[gid];
        __nv_bfloat16 hb = __float2bfloat16_rn(w);
        float r = w - __bfloat162float(hb);
        g_Whi[gid] = hb;
        g_Wlo[gid] = __float2bfloat16_rn(r);
    }
}

// ---------------- kernel 2: ELL fill (atomicAdd allocates slots) ----------------
__global__ void k_fill(const int* __restrict__ ei, int n_edges) {
    int e = blockIdx.x * blockDim.x + threadIdx.x;
    if (e >= n_edges) return;
    int s = ei[e];
    int d = ei[n_edges + e];
    int p0 = atomicAdd(&g_cnt[s], 1);
    g_adj[s * ELL + p0] = d;
    int p1 = atomicAdd(&g_cnt[d], 1);
    g_adj[d * ELL + p1] = s;
}

// ---------------- kernel 3: gather-reduce: warp per node, writes MEAN ----------------
__global__ __launch_bounds__(256)
void k_gather(const float2* __restrict__ feat2, int n_nodes) {
    int w = (blockIdx.x * blockDim.x + threadIdx.x) >> 5;
    if (w >= n_nodes) return;
    int lane = threadIdx.x & 31;
    int deg = g_cnt[w];
    const int* row = &g_adj[w * ELL];     // 256B aligned

    float2 acc = make_float2(0.f, 0.f);
    int j = 0;
    for (; j + 4 <= deg; j += 4) {
        int4 i4 = *(const int4*)&row[j];  // one LDG.128 for 4 indices
        float2 a = feat2[(size_t)i4.x * 32 + lane];
        float2 b = feat2[(size_t)i4.y * 32 + lane];
        float2 c = feat2[(size_t)i4.z * 32 + lane];
        float2 d = feat2[(size_t)i4.w * 32 + lane];
        acc.x += a.x + b.x + c.x + d.x;
        acc.y += a.y + b.y + c.y + d.y;
    }
    for (; j < deg; ++j) {
        float2 a = feat2[(size_t)row[j] * 32 + lane];
        acc.x += a.x;
        acc.y += a.y;
    }
    float inv = 1.0f / fmaxf((float)deg, 1.0f);
    acc.x *= inv;
    acc.y *= inv;
    g_mean2[(size_t)w * 32 + lane] = acc;
}

// ---------------- kernel 4: wmma GEMM (3xBF16 split) ----------------
// BM=64 rows/block, 128 threads (4 warps), warp tile 32x64 (2x4 fragments).
// smem = 104448 B -> 2 CTAs resident per SM (cross-block phase overlap).
// out[m][h] = relu( combined[m] . W[h] + b[h] ), via
//   hi@Whi + hi@Wlo + lo@Whi   (fp32 accumulate)
#define BM 64
#define ASTRIDE 136
#define A_ELEMS (BM * ASTRIDE)                // 8704 bf16 (17408 B)
#define B_ELEMS (128 * ASTRIDE)               // 17408 bf16 (34816 B)
#define SMEM_DYN ((2 * A_ELEMS + 2 * B_ELEMS) * 2)   // 104448 bytes

__global__ __launch_bounds__(128, 2)
void gemm_kernel(const float4* __restrict__ feat4,
                 const int* __restrict__ nodes,
                 const float* __restrict__ bias,
                 float* __restrict__ out,
                 int n_rows) {
    extern __shared__ __nv_bfloat16 smem[];
    __nv_bfloat16* Ahi = smem;
    __nv_bfloat16* Alo = smem + A_ELEMS;
    __nv_bfloat16* Bhi = smem + 2 * A_ELEMS;
    __nv_bfloat16* Blo = smem + 2 * A_ELEMS + B_ELEMS;

    int tid = threadIdx.x;
    int block_m = blockIdx.x * BM;

    // ---- stage pre-split W, col-major: Bs[k + h*ASTRIDE] ----
    // uint4 = 8 bf16 along k; dst byte offset 272h + 16kq -> 16B aligned.
    {
        const uint4* shi = (const uint4*)g_Whi;
        const uint4* slo = (const uint4*)g_Wlo;
        #pragma unroll
        for (int i = 0; i < (HH * KK / 8) / 128; ++i) {
            int idx = tid + i * 128;          // octet index
            int h = idx >> 4;                 // 16 octets per h
            int k = (idx & 15) * 8;
            *(uint4*)&Bhi[k + h * ASTRIDE] = shi[idx];
            *(uint4*)&Blo[k + h * ASTRIDE] = slo[idx];
        }
    }

    // ---- gather + split combined rows ----
    // 2 threads per row: half 0 = self feats (k 0..63), half 1 = neigh mean
    {
        int r = tid >> 1;
        int half = tid & 1;
        int row = block_m + r;
        bool valid = row < n_rows;
        int g = valid ? nodes[row] : 0;
        const float4* src = half ? (const float4*)&g_mean2[(size_t)g * 32]
                                 : &feat4[(size_t)g * 16];

        #pragma unroll
        for (int q = 0; q < 8; ++q) {         // 8 chunks of 8 bf16
            uint4 hi = make_uint4(0, 0, 0, 0), lo = make_uint4(0, 0, 0, 0);
            if (valid) {
                float4 u = src[2 * q];
                float4 v = src[2 * q + 1];
                cvt2_split(u.x, u.y, hi.x, lo.x);
                cvt2_split(u.z, u.w, hi.y, lo.y);
                cvt2_split(v.x, v.y, hi.z, lo.z);
                cvt2_split(v.z, v.w, hi.w, lo.w);
            }
            int off = r * ASTRIDE + half * 64 + q * 8;
            *(uint4*)&Ahi[off] = hi;
            *(uint4*)&Alo[off] = lo;
        }
    }
    __syncthreads();

    // ---- wmma: 4 warps, warp tile 32x64 (2 x 4 fragments of 16x16) ----
    int wid = tid >> 5;
    int wm = wid & 1;      // 0..1 -> rows wm*32
    int wn = wid >> 1;     // 0..1 -> cols wn*64

    wmma::fragment<wmma::accumulator, 16, 16, 16, float> acc[2][4];
    #pragma unroll
    for (int i = 0; i < 2; ++i)
        #pragma unroll
        for (int j = 0; j < 4; ++j) wmma::fill_fragment(acc[i][j], 0.0f);

    const __nv_bfloat16* Aptr[3] = {Ahi, Ahi, Alo};
    const __nv_bfloat16* Bptr[3] = {Bhi, Blo, Bhi};

    #pragma unroll
    for (int pass = 0; pass < 3; ++pass) {
        const __nv_bfloat16* As = Aptr[pass];
        const __nv_bfloat16* Bs = Bptr[pass];
        #pragma unroll
        for (int k0 = 0; k0 < KK; k0 += 16) {
            wmma::fragment<wmma::matrix_a, 16, 16, 16, __nv_bfloat16, wmma::row_major> af[2];
            wmma::fragment<wmma::matrix_b, 16, 16, 16, __nv_bfloat16, wmma::col_major> bf[4];
            #pragma unroll
            for (int i = 0; i < 2; ++i)
                wmma::load_matrix_sync(af[i], As + (wm * 32 + i * 16) * ASTRIDE + k0, ASTRIDE);
            #pragma unroll
            for (int j = 0; j < 4; ++j)
                wmma::load_matrix_sync(bf[j], Bs + k0 + (wn * 64 + j * 16) * ASTRIDE, ASTRIDE);
            #pragma unroll
            for (int i = 0; i < 2; ++i)
                #pragma unroll
                for (int j = 0; j < 4; ++j)
                    wmma::mma_sync(acc[i][j], af[i], bf[j], acc[i][j]);
        }
    }

    // ---- stage accumulators to smem (reuse tile region), then epilogue ----
    __syncthreads();   // all warps done reading A/B tiles
    float* stage = (float*)smem;                   // 4 warps x 32x64 f32 = 32KB
    float* wstage = stage + wid * (32 * 64);
    #pragma unroll
    for (int i = 0; i < 2; ++i)
        #pragma unroll
        for (int j = 0; j < 4; ++j)
            wmma::store_matrix_sync(wstage + i * 16 * 64 + j * 16, acc[i][j],
                                    64, wmma::mem_row_major);
    __syncwarp();

    // each lane writes one row of the warp tile (32 rows x 64 cols)
    {
        int lane = tid & 31;
        int row = block_m + wm * 32 + lane;
        if (row < n_rows) {
            const float* srow = wstage + lane * 64;
            float* orow = out + (size_t)row * HH + wn * 64;
            #pragma unroll
            for (int c = 0; c < 64; c += 4) {
                float4 o;
                o.x = fmaxf(srow[c + 0] + bias[wn * 64 + c + 0], 0.f);
                o.y = fmaxf(srow[c + 1] + bias[wn * 64 + c + 1], 0.f);
                o.z = fmaxf(srow[c + 2] + bias[wn * 64 + c + 2], 0.f);
                o.w = fmaxf(srow[c + 3] + bias[wn * 64 + c + 3], 0.f);
                *(float4*)&orow[c] = o;
            }
        }
    }
}

// ---------------- launch ----------------
extern "C" void kernel_launch(void* const* d_in, const int* in_sizes, int n_in,
                              void* d_out, int out_size) {
    const int*    nodes    = (const int*)d_in[0];
    const float*  features = (const float*)d_in[1];
    const int*    ei       = (const int*)d_in[2];
    const float*  W        = (const float*)d_in[3];
    const float*  bias     = (const float*)d_in[4];
    float*        out      = (float*)d_out;

    int n_rows  = in_sizes[0];           // B == N
    int n_nodes = in_sizes[1] / DD;      // N
    int n_edges = in_sizes[2] / 2;       // E

    const float4* feat4 = (const float4*)features;
    const float2* feat2 = (const float2*)features;

    // opt-in to >48KB dynamic smem (immediate host-side call, idempotent)
    cudaFuncSetAttribute(gemm_kernel,
                         cudaFuncAttributeMaxDynamicSharedMemorySize, SMEM_DYN);

    // 1. zero counters + split W
    {
        int total = n_nodes > HH * KK ? n_nodes : HH * KK;
        prep_kernel<<<(total + 255) / 256, 256>>>(W, n_nodes);
    }
    // 2. ELL fill
    k_fill<<<(n_edges + 255) / 256, 256>>>(ei, n_edges);
    // 3. gather-reduce (writes means)
    k_gather<<<(n_nodes * 32 + 255) / 256, 256>>>(feat2, n_nodes);
    // 4. wmma GEMM (concat fused into gather stage)
    {
        int blocks = (n_rows + BM - 1) / BM;
        gemm_kernel<<<blocks, 128, SMEM_DYN>>>(feat4, nodes, bias, out, n_rows);
    }
}